// round 2
// baseline (speedup 1.0000x reference)
#include <cuda_runtime.h>
#include <stdint.h>

// FP32 bit-pulse -> FP8 E4M3 bit-pulse converter, warp-cooperative version.
//
// Input : N*32 floats (0.0f/1.0f), row = [S, E7..E0, M22..M0] MSB first
// Output: N*8  floats, row = [S, E3..E0, M2..M0]
//
// Each warp handles 32 consecutive rows (a 4 KB contiguous tile). 8 coalesced
// LDG.128 passes; pass p covers rows 4p..4p+3 (one row per lane-octet). Each
// lane turns its uint4 into a 4-bit nibble (bit 29 of 1.0f), a per-octet
// reduce_or assembles the row's packed IEEE word, and a shuffle hands row r's
// word to lane r. Lane r then does the E4M3 RNE conversion for its row and
// stores 8 floats with two STG.128.

__global__ __launch_bounds__(256) void fp32_to_fp8_pulse_kernel(
    const uint4* __restrict__ in,   // 8 x uint4 per row
    float4* __restrict__ out,       // 2 x float4 per row
    int nrows)
{
    const int lane    = threadIdx.x & 31;
    const int baserow = (blockIdx.x * blockDim.x + threadIdx.x) - lane; // warp's first row
    if (baserow >= nrows) return;

    // ---- coalesced tile load: 8 x LDG.128, 512 B contiguous per warp-pass ----
    const uint4* tile = in + (size_t)baserow * 8;
    uint4 v[8];
#pragma unroll
    for (int p = 0; p < 8; p++) v[p] = tile[p * 32 + lane];

    const int k = lane & 7;                               // word-group within row
    const uint32_t octmask = 0xFFu << ((lane >> 3) << 3); // this lane's octet
    const int srcLane = (lane & 3) << 3;                  // octet leader holding my row
    const int mypass  = lane >> 2;                        // pass that produces my row

    uint32_t packed = 0;
#pragma unroll
    for (int p = 0; p < 8; p++) {
        uint32_t nib = (((v[p].x >> 29) & 1u) << 3)
                     | (((v[p].y >> 29) & 1u) << 2)
                     | (((v[p].z >> 29) & 1u) << 1)
                     |  ((v[p].w >> 29) & 1u);
        uint32_t contrib = nib << (28 - 4 * k);
        uint32_t rowword = __reduce_or_sync(octmask, contrib); // row 4p+(lane>>3)
        uint32_t t = __shfl_sync(0xFFFFFFFFu, rowword, srcLane);
        if (mypass == p) packed = t;                      // lane r keeps row r
    }

    const int row = baserow + lane;
    if (row >= nrows) return;

    // ---- E4M3 conversion (bit-exact vs reference) ----
    uint32_t s    = packed >> 31;
    uint32_t exp  = (packed >> 23) & 0xFFu;
    uint32_t mant = packed & 0x7FFFFFu;

    // normal path: RNE round 23 -> 3 mantissa bits
    uint32_t kept = mant >> 20;
    uint32_t R    = (mant >> 19) & 1u;
    uint32_t S    = (mant & ((1u << 19) - 1u)) != 0u;
    uint32_t L    = kept & 1u;
    uint32_t mr   = kept + (R & (S | L));
    uint32_t carry = mr >> 3;
    uint32_t mant_norm = carry ? 0u : (mr & 7u);
    uint32_t exp_norm  = exp - 120u + carry;

    // subnormal path (117 <= exp <= 120)
    uint32_t full = (1u << 23) | mant;
    int shi = 141 - (int)exp;
    if (shi < 1)  shi = 1;
    if (shi > 24) shi = 24;
    uint32_t sh = (uint32_t)shi;
    uint32_t kept_s = full >> sh;
    uint32_t Rs = (full >> (sh - 1u)) & 1u;
    uint32_t Ss = (full & ((1u << (sh - 1u)) - 1u)) != 0u;
    uint32_t Ls = kept_s & 1u;
    uint32_t ms = kept_s + (Rs & (Ss | Ls));
    uint32_t sub_exp  = (ms >= 8u) ? 1u : 0u;
    uint32_t sub_mant = (ms >= 8u) ? 0u : ms;

    uint32_t exp8, mant8;
    if (exp > 134u)                      { exp8 = 15u;      mant8 = 6u;        }
    else if (exp >= 117u && exp <= 120u) { exp8 = sub_exp;  mant8 = sub_mant;  }
    else if (exp < 117u)                 { exp8 = 0u;       mant8 = 0u;        }
    else                                 { exp8 = exp_norm; mant8 = mant_norm; }

    float4 o0, o1;
    o0.x = (float)s;
    o0.y = (float)((exp8 >> 3) & 1u);
    o0.z = (float)((exp8 >> 2) & 1u);
    o0.w = (float)((exp8 >> 1) & 1u);
    o1.x = (float)(exp8 & 1u);
    o1.y = (float)((mant8 >> 2) & 1u);
    o1.z = (float)((mant8 >> 1) & 1u);
    o1.w = (float)(mant8 & 1u);

    out[(size_t)row * 2]     = o0;
    out[(size_t)row * 2 + 1] = o1;
}

extern "C" void kernel_launch(void* const* d_in, const int* in_sizes, int n_in,
                              void* d_out, int out_size)
{
    const uint4* in = (const uint4*)d_in[0];
    float4* out = (float4*)d_out;
    int nrows = in_sizes[0] / 32;

    int threads = 256;
    int blocks = (nrows + threads - 1) / threads;
    fp32_to_fp8_pulse_kernel<<<blocks, threads>>>(in, out, nrows);
}

// round 3
// speedup vs baseline: 1.3148x; 1.3148x over previous
#include <cuda_runtime.h>
#include <stdint.h>

// FP32 bit-pulse -> FP8 E4M3 bit-pulse converter.
// Input : N*32 floats (0.0f/1.0f), row = [S, E7..E0, M22..M0] MSB first
// Output: N*8  floats, row = [S, E3..E0, M2..M0]
//
// Warp-cooperative, smem-staged transpose:
//  - warp owns 32 consecutive rows (4 KB contiguous input)
//  - 8 coalesced LDG.128 passes; each lane reduces its uint4 to one 4-bit
//    nibble (bit 29 of 1.0f) and byte-stores it at smem[p*32+lane], which is
//    exactly row-major nibble order (row = (p*32+lane)/8, col = %8)
//  - lane r reads its row's 8 nibble-bytes with one LDS.64 (conflict-free),
//    packs them into the IEEE754 word, converts, stores.

__device__ __forceinline__ void convert_row(uint32_t packed, uint32_t s,
                                            float4& o0, float4& o1)
{
    uint32_t exp  = (packed >> 23) & 0xFFu;
    uint32_t mant = packed & 0x7FFFFFu;

    // normal path: RNE round 23 -> 3 mantissa bits
    uint32_t kept = mant >> 20;
    uint32_t R    = (mant >> 19) & 1u;
    uint32_t S    = (mant & ((1u << 19) - 1u)) != 0u;
    uint32_t L    = kept & 1u;
    uint32_t mr   = kept + (R & (S | L));
    uint32_t carry = mr >> 3;
    uint32_t mant_norm = carry ? 0u : (mr & 7u);
    uint32_t exp_norm  = exp - 120u + carry;

    // subnormal path (117 <= exp <= 120)
    uint32_t full = (1u << 23) | mant;
    int shi = 141 - (int)exp;
    if (shi < 1)  shi = 1;
    if (shi > 24) shi = 24;
    uint32_t sh = (uint32_t)shi;
    uint32_t kept_s = full >> sh;
    uint32_t Rs = (full >> (sh - 1u)) & 1u;
    uint32_t Ss = (full & ((1u << (sh - 1u)) - 1u)) != 0u;
    uint32_t Ls = kept_s & 1u;
    uint32_t ms = kept_s + (Rs & (Ss | Ls));
    uint32_t sub_exp  = (ms >= 8u) ? 1u : 0u;
    uint32_t sub_mant = (ms >= 8u) ? 0u : ms;

    uint32_t exp8, mant8;
    if (exp > 134u)                      { exp8 = 15u;      mant8 = 6u;        }
    else if (exp >= 117u && exp <= 120u) { exp8 = sub_exp;  mant8 = sub_mant;  }
    else if (exp < 117u)                 { exp8 = 0u;       mant8 = 0u;        }
    else                                 { exp8 = exp_norm; mant8 = mant_norm; }

    o0.x = (float)s;
    o0.y = (float)((exp8 >> 3) & 1u);
    o0.z = (float)((exp8 >> 2) & 1u);
    o0.w = (float)((exp8 >> 1) & 1u);
    o1.x = (float)(exp8 & 1u);
    o1.y = (float)((mant8 >> 2) & 1u);
    o1.z = (float)((mant8 >> 1) & 1u);
    o1.w = (float)(mant8 & 1u);
}

__global__ __launch_bounds__(256) void fp32_to_fp8_pulse_kernel(
    const uint4* __restrict__ in,   // 8 x uint4 per row
    float4* __restrict__ out,       // 2 x float4 per row
    int nrows)
{
    __shared__ uint8_t snib[8][256];   // per-warp: 32 rows x 8 nibble-bytes

    const int warp = threadIdx.x >> 5;
    const int lane = threadIdx.x & 31;
    const int baserow = (blockIdx.x * 8 + warp) * 32;
    if (baserow >= nrows) return;

    if (baserow + 32 <= nrows) {
        // ---- fast path: full 32-row tile ----
        const uint4* tile = in + (size_t)baserow * 8;

        // coalesced loads; each lane stores one nibble-byte per pass.
        // smem index p*32+lane == row-major (row=(p*32+lane)/8, col=%8).
#pragma unroll
        for (int p = 0; p < 8; p++) {
            uint4 v = tile[p * 32 + lane];
            uint32_t nib = (((v.x >> 29) & 1u) << 3)
                         | (((v.y >> 29) & 1u) << 2)
                         | (((v.z >> 29) & 1u) << 1)
                         |  ((v.w >> 29) & 1u);
            snib[warp][p * 32 + lane] = (uint8_t)nib;
        }
        __syncwarp();

        // lane r: one LDS.64 fetches row r's 8 nibbles (bytes 8r..8r+7)
        uint2 u = *reinterpret_cast<const uint2*>(&snib[warp][lane * 8]);

        // pack: byte j = nibble of column j (MSB-first groups of 4 bits)
        uint32_t hi = ((u.x & 0x0000000Fu) << 28)
                    | ((u.x & 0x00000F00u) << 16)
                    | ((u.x & 0x000F0000u) << 4)
                    | ((u.x & 0x0F000000u) >> 8);
        uint32_t lo = ((u.y & 0x0000000Fu) << 12)
                    | ((u.y & 0x00000F00u) >> 0)
                    | ((u.y & 0x000F0000u) >> 12)
                    | ((u.y & 0x0F000000u) >> 24);
        uint32_t packed = hi | lo;

        float4 o0, o1;
        convert_row(packed, packed >> 31, o0, o1);

        const int row = baserow + lane;
        out[(size_t)row * 2]     = o0;
        out[(size_t)row * 2 + 1] = o1;
    } else {
        // ---- tail path: per-thread row (round-1 style) ----
        const int row = baserow + lane;
        if (row >= nrows) return;
        const uint4* p = in + (size_t)row * 8;
        uint32_t packed = 0;
#pragma unroll
        for (int k = 0; k < 8; k++) {
            uint4 v = p[k];
            uint32_t nib = (((v.x >> 29) & 1u) << 3)
                         | (((v.y >> 29) & 1u) << 2)
                         | (((v.z >> 29) & 1u) << 1)
                         |  ((v.w >> 29) & 1u);
            packed = (packed << 4) | nib;
        }
        float4 o0, o1;
        convert_row(packed, packed >> 31, o0, o1);
        out[(size_t)row * 2]     = o0;
        out[(size_t)row * 2 + 1] = o1;
    }
}

extern "C" void kernel_launch(void* const* d_in, const int* in_sizes, int n_in,
                              void* d_out, int out_size)
{
    const uint4* in = (const uint4*)d_in[0];
    float4* out = (float4*)d_out;
    int nrows = in_sizes[0] / 32;

    int threads = 256;
    int blocks = (nrows + threads - 1) / threads;
    fp32_to_fp8_pulse_kernel<<<blocks, threads>>>(in, out, nrows);
}